// round 2
// baseline (speedup 1.0000x reference)
#include <cuda_runtime.h>
#include <cstdint>

// ============================================================================
// TF32 mma.sync GEMM (portable sm_80+ path; tcgen05 rejected by compute_103
// virtual target): out[32768,512] = X @ W^T + bias.
// BM=128, BN=128, BK=32, 8 warps (4x2), warp tile 32x64, m16n8k8 tf32.
// cp.async double-buffered smem, stride 36 floats (16B aligned, conflict-free).
// ============================================================================

#define MTOT 32768
#define KTOT 512
#define NTOT 512
#define BM   128
#define BN   128
#define BK   32
#define NKC  (KTOT / BK)     // 16
#define THREADS 256
#define SSTRIDE 36           // floats per smem row (32 data + 4 pad)

#define TILE_FLOATS (128 * SSTRIDE)     // 4608 floats per operand tile

__device__ __forceinline__ uint32_t smem_u32(const void* p) {
    return (uint32_t)__cvta_generic_to_shared(p);
}

__device__ __forceinline__ uint32_t tf32rn(float x) {
    uint32_t y;
    asm("cvt.rna.tf32.f32 %0, %1;" : "=r"(y) : "f"(x));
    return y;
}

#define CP_ASYNC_CG(dst_u32, src_ptr)                                         \
    asm volatile("cp.async.cg.shared.global [%0], [%1], 16;"                  \
                 :: "r"(dst_u32), "l"(src_ptr))
#define CP_COMMIT() asm volatile("cp.async.commit_group;" ::: "memory")
#define CP_WAIT(N)  asm volatile("cp.async.wait_group %0;" :: "n"(N) : "memory")

__device__ __forceinline__ void mma_tf32(float* d, const uint32_t* a,
                                         const uint32_t* b) {
    asm volatile(
        "mma.sync.aligned.m16n8k8.row.col.f32.tf32.tf32.f32 "
        "{%0,%1,%2,%3}, {%4,%5,%6,%7}, {%8,%9}, {%0,%1,%2,%3};"
        : "+f"(d[0]), "+f"(d[1]), "+f"(d[2]), "+f"(d[3])
        : "r"(a[0]), "r"(a[1]), "r"(a[2]), "r"(a[3]), "r"(b[0]), "r"(b[1]));
}

__global__ void __launch_bounds__(THREADS, 2)
linear_tf32_kernel(const float* __restrict__ X, const float* __restrict__ W,
                   const float* __restrict__ bias, float* __restrict__ out) {
    extern __shared__ float smem[];
    float* As = smem;                       // [2][TILE_FLOATS]
    float* Bs = smem + 2 * TILE_FLOATS;     // [2][TILE_FLOATS]
    float* bias_s = smem + 4 * TILE_FLOATS; // [BN]

    const int tid = threadIdx.x;
    const int wid = tid >> 5;
    const int lid = tid & 31;
    const int g = lid >> 2;          // group id (0..7)
    const int t = lid & 3;           // thread-in-group (0..3)
    const int wm = (wid & 3) * 32;   // warp M offset within CTA tile
    const int wn = (wid >> 2) * 64;  // warp N offset within CTA tile

    const int n0 = blockIdx.x * BN;
    const int m0 = blockIdx.y * BM;

    const float* Ag = X + (size_t)m0 * KTOT;
    const float* Bg = W + (size_t)n0 * KTOT;

    if (tid < BN) bias_s[tid] = bias[n0 + tid];

    const uint32_t as_base = smem_u32(As);
    const uint32_t bs_base = smem_u32(Bs);

    // Per-thread cp.async assignments: 4 chunks of A, 4 of B per tile.
    // idx in [0,1024): row = idx>>3, chunk = idx&7 (16B chunks of a 128B row).
    // -------- prologue: stage 0 --------
    {
        #pragma unroll
        for (int i = 0; i < 4; i++) {
            const int idx = tid + i * THREADS;
            const int row = idx >> 3, ch = idx & 7;
            CP_ASYNC_CG(as_base + (row * SSTRIDE + ch * 4) * 4,
                        Ag + (size_t)row * KTOT + ch * 4);
        }
        #pragma unroll
        for (int i = 0; i < 4; i++) {
            const int idx = tid + i * THREADS;
            const int row = idx >> 3, ch = idx & 7;
            CP_ASYNC_CG(bs_base + (row * SSTRIDE + ch * 4) * 4,
                        Bg + (size_t)row * KTOT + ch * 4);
        }
        CP_COMMIT();
    }

    float acc[2][8][4];
    #pragma unroll
    for (int mi = 0; mi < 2; mi++)
        #pragma unroll
        for (int nj = 0; nj < 8; nj++)
            #pragma unroll
            for (int e = 0; e < 4; e++) acc[mi][nj][e] = 0.0f;

    for (int kc = 0; kc < NKC; kc++) {
        const int s = kc & 1;

        // Prefetch next tile into the other stage.
        if (kc + 1 < NKC) {
            const int sn = s ^ 1;
            const int kb = (kc + 1) * BK;
            const uint32_t an = as_base + sn * TILE_FLOATS * 4;
            const uint32_t bn = bs_base + sn * TILE_FLOATS * 4;
            #pragma unroll
            for (int i = 0; i < 4; i++) {
                const int idx = tid + i * THREADS;
                const int row = idx >> 3, ch = idx & 7;
                CP_ASYNC_CG(an + (row * SSTRIDE + ch * 4) * 4,
                            Ag + (size_t)row * KTOT + kb + ch * 4);
            }
            #pragma unroll
            for (int i = 0; i < 4; i++) {
                const int idx = tid + i * THREADS;
                const int row = idx >> 3, ch = idx & 7;
                CP_ASYNC_CG(bn + (row * SSTRIDE + ch * 4) * 4,
                            Bg + (size_t)row * KTOT + kb + ch * 4);
            }
            CP_COMMIT();
            CP_WAIT(1);   // current tile (group kc) complete
        } else {
            CP_WAIT(0);
        }
        __syncthreads();

        const float* At = As + s * TILE_FLOATS;
        const float* Bt = Bs + s * TILE_FLOATS;

        #pragma unroll
        for (int ks = 0; ks < 4; ks++) {
            const int k = ks * 8;
            uint32_t af[2][4];
            #pragma unroll
            for (int mi = 0; mi < 2; mi++) {
                const int r = wm + mi * 16 + g;
                af[mi][0] = tf32rn(At[r * SSTRIDE + k + t]);
                af[mi][1] = tf32rn(At[(r + 8) * SSTRIDE + k + t]);
                af[mi][2] = tf32rn(At[r * SSTRIDE + k + t + 4]);
                af[mi][3] = tf32rn(At[(r + 8) * SSTRIDE + k + t + 4]);
            }
            uint32_t bf[8][2];
            #pragma unroll
            for (int nj = 0; nj < 8; nj++) {
                const int n = wn + nj * 8 + g;
                bf[nj][0] = tf32rn(Bt[n * SSTRIDE + k + t]);
                bf[nj][1] = tf32rn(Bt[n * SSTRIDE + k + t + 4]);
            }
            #pragma unroll
            for (int mi = 0; mi < 2; mi++)
                #pragma unroll
                for (int nj = 0; nj < 8; nj++)
                    mma_tf32(acc[mi][nj], af[mi], bf[nj]);
        }
        __syncthreads();
    }

    // -------- epilogue: add bias, store float2 --------
    #pragma unroll
    for (int mi = 0; mi < 2; mi++) {
        const int r0 = m0 + wm + mi * 16 + g;
        #pragma unroll
        for (int nj = 0; nj < 8; nj++) {
            const int cl = wn + nj * 8 + 2 * t;      // col within CTA tile
            const float bx = bias_s[cl];
            const float by = bias_s[cl + 1];
            float2 v0 = make_float2(acc[mi][nj][0] + bx, acc[mi][nj][1] + by);
            float2 v1 = make_float2(acc[mi][nj][2] + bx, acc[mi][nj][3] + by);
            *reinterpret_cast<float2*>(out + (size_t)r0 * NTOT + n0 + cl) = v0;
            *reinterpret_cast<float2*>(out + (size_t)(r0 + 8) * NTOT + n0 + cl) = v1;
        }
    }
}

#define SMEM_BYTES ((4 * TILE_FLOATS + BN) * 4)

extern "C" void kernel_launch(void* const* d_in, const int* in_sizes, int n_in,
                              void* d_out, int out_size) {
    const float* X    = (const float*)d_in[0];
    const float* Wt   = (const float*)d_in[1];
    const float* bias = (const float*)d_in[2];
    float* out = (float*)d_out;

    const int Mrows = in_sizes[0] / KTOT;   // 32768

    cudaFuncSetAttribute(linear_tf32_kernel,
                         cudaFuncAttributeMaxDynamicSharedMemorySize, SMEM_BYTES);

    dim3 grid(NTOT / BN, Mrows / BM);  // (4, 256)
    linear_tf32_kernel<<<grid, THREADS, SMEM_BYTES>>>(X, Wt, bias, out);
}